// round 4
// baseline (speedup 1.0000x reference)
#include <cuda_runtime.h>
#include <cuda_bf16.h>
#include <stdint.h>

// Problem constants: B=S=H=DH=64, D = H*DH = 4096
static const int DFEAT = 4096;
static const int NTOK  = 4096;

// int8 GEMM tiling: BM=BN=128, BK=128 int8 bytes, 3-stage cp.async pipeline
static const int BKB  = 128;                 // k bytes (=elements) per stage
static const int NKT  = DFEAT / BKB;         // 32
static const int TILE_BYTES  = 128 * 128;    // 128 rows x 128 int8 = 16KB
static const int STAGE_BYTES = 4 * TILE_BYTES;   // Ah, Al, Bh, Bl = 64KB
static const int SMEM_BYTES  = 3 * STAGE_BYTES;  // 192KB

// Scratch (static device arrays; no allocation allowed)
__device__ float   g_qkv[3ull * (size_t)NTOK * DFEAT];
__device__ float   g_merged[(size_t)NTOK * DFEAT];
__device__ int8_t  g_xh[(size_t)NTOK * DFEAT];
__device__ int8_t  g_xl[(size_t)NTOK * DFEAT];
__device__ int8_t  g_wh[4ull * (size_t)DFEAT * DFEAT];
__device__ int8_t  g_wl[4ull * (size_t)DFEAT * DFEAT];
__device__ int8_t  g_mh[(size_t)NTOK * DFEAT];
__device__ int8_t  g_ml[(size_t)NTOK * DFEAT];
__device__ float   g_sx[NTOK];
__device__ float   g_sw[4 * DFEAT];
__device__ float   g_sm[NTOK];

struct GArgs {
    const int8_t* Ah;
    const int8_t* Al;
    const float*  sa;
    const int8_t* Bh[3];
    const int8_t* Bl[3];
    const float*  sb[3];
    const float*  bias[3];
    float*        C[3];
};

// ---------------- helpers ----------------
__device__ __forceinline__ uint32_t smem_u32(const void* p) {
    uint32_t a;
    asm("{ .reg .u64 t; cvta.to.shared.u64 t, %1; cvt.u32.u64 %0, t; }" : "=r"(a) : "l"(p));
    return a;
}
__device__ __forceinline__ void cp16(uint32_t dst, const void* src) {
    asm volatile("cp.async.cg.shared.global [%0], [%1], 16;" :: "r"(dst), "l"(src) : "memory");
}
__device__ __forceinline__ void cp_commit() {
    asm volatile("cp.async.commit_group;" ::: "memory");
}
template <int N>
__device__ __forceinline__ void cp_wait() {
    asm volatile("cp.async.wait_group %0;" :: "n"(N) : "memory");
}
__device__ __forceinline__ void ldsm4(uint32_t* r, uint32_t a) {
    asm volatile("ldmatrix.sync.aligned.m8n8.x4.shared.b16 {%0,%1,%2,%3}, [%4];"
                 : "=r"(r[0]), "=r"(r[1]), "=r"(r[2]), "=r"(r[3]) : "r"(a));
}
// m16n8k32 int8 mma, s32 accumulate
__device__ __forceinline__ void imma(int c[4], const uint32_t a[4], const uint32_t b[2]) {
    asm volatile(
        "mma.sync.aligned.m16n8k32.row.col.s32.s8.s8.s32 "
        "{%0,%1,%2,%3}, {%4,%5,%6,%7}, {%8,%9}, {%0,%1,%2,%3};\n"
        : "+r"(c[0]), "+r"(c[1]), "+r"(c[2]), "+r"(c[3])
        : "r"(a[0]), "r"(a[1]), "r"(a[2]), "r"(a[3]), "r"(b[0]), "r"(b[1]));
}

// ---------------- per-row fixed-point quantization ----------------
// row value v -> q = round(v/s), q = h*128 + l, h,l in int8, s = rowmax/16256
__global__ __launch_bounds__(256) void quant_rows(const float* __restrict__ src,
                                                  int8_t* __restrict__ qh,
                                                  int8_t* __restrict__ ql,
                                                  float* __restrict__ scale) {
    __shared__ float red[8];
    const int row = blockIdx.x;
    const int t   = threadIdx.x;
    const float4* p = (const float4*)(src + (size_t)row * DFEAT);

    float4 v[4];
    float mx = 0.0f;
    #pragma unroll
    for (int i = 0; i < 4; ++i) {
        v[i] = p[t * 4 + i];
        mx = fmaxf(mx, fmaxf(fmaxf(fabsf(v[i].x), fabsf(v[i].y)),
                             fmaxf(fabsf(v[i].z), fabsf(v[i].w))));
    }
    #pragma unroll
    for (int off = 16; off >= 1; off >>= 1)
        mx = fmaxf(mx, __shfl_xor_sync(0xffffffffu, mx, off));
    if ((t & 31) == 0) red[t >> 5] = mx;
    __syncthreads();
    if (t == 0) {
        float m = red[0];
        #pragma unroll
        for (int i = 1; i < 8; ++i) m = fmaxf(m, red[i]);
        red[0] = m;
        scale[row] = m * (1.0f / 16256.0f);
    }
    __syncthreads();
    const float m = red[0];
    const float inv = (m > 0.0f) ? (16256.0f / m) : 0.0f;

    uint8_t hb[16], lb[16];
    #pragma unroll
    for (int i = 0; i < 4; ++i) {
        const float* f = (const float*)&v[i];
        #pragma unroll
        for (int j = 0; j < 4; ++j) {
            int q = __float2int_rn(f[j] * inv);
            int h = (q + 64) >> 7;           // round-to-nearest of q/128
            int l = q - (h << 7);            // in [-64, 63]
            hb[i * 4 + j] = (uint8_t)(int8_t)h;
            lb[i * 4 + j] = (uint8_t)(int8_t)l;
        }
    }
    *(int4*)(qh + (size_t)row * DFEAT + t * 16) = *(const int4*)hb;
    *(int4*)(ql + (size_t)row * DFEAT + t * 16) = *(const int4*)lb;
}

// ---------------- int8x2 IMMA GEMM ----------------
// C[m][n] = sa[m]*sb[n]*(HH*16384 + MID*128) + bias[n]
// 256 threads, warp grid 2(M) x 4(N), warp tile 64x32, BM=BN=128, BK=128 int8.
__global__ __launch_bounds__(256, 1) void gemm_imma(GArgs g) {
    extern __shared__ __align__(1024) char smem[];
    const int z = blockIdx.z;
    const int8_t* __restrict__ Ah = g.Ah;
    const int8_t* __restrict__ Al = g.Al;
    const int8_t* __restrict__ Bh = g.Bh[z];
    const int8_t* __restrict__ Bl = g.Bl[z];
    const float* __restrict__ sa   = g.sa;
    const float* __restrict__ sb   = g.sb[z];
    const float* __restrict__ bias = g.bias[z];
    float* __restrict__ C = g.C[z];

    const int tid  = threadIdx.x;
    const int lane = tid & 31;
    const int wid  = tid >> 5;
    const int wm = (wid & 1) * 64;
    const int wn = (wid >> 1) * 32;
    const int m0 = blockIdx.y * 128;
    const int n0 = blockIdx.x * 128;
    const uint32_t sb_addr = smem_u32(smem);

    // ---- loader mapping: 4 ids per thread, each id = one 16B chunk per tile ----
    uint32_t doff[4];
    int      goff[4];
    #pragma unroll
    for (int i = 0; i < 4; ++i) {
        const int id = tid + i * 256;
        const int r  = id >> 3;      // 0..127
        const int c  = id & 7;       // 16B chunk within 128B row
        doff[i] = (uint32_t)(r * 128 + ((c ^ (r & 7)) << 4));
        goff[i] = r * DFEAT + c * 16;  // byte offset
    }
    const int8_t* pAh = Ah + (size_t)m0 * DFEAT;
    const int8_t* pAl = Al + (size_t)m0 * DFEAT;
    const int8_t* pBh = Bh + (size_t)n0 * DFEAT;
    const int8_t* pBl = Bl + (size_t)n0 * DFEAT;

    // ---- ldmatrix lane mapping (identical chunk-permute trick as bf16 ver) ----
    uint32_t aoff[4], amask[4];
    const int asel = lane >> 4;          // 16B chunk select within k32
    #pragma unroll
    for (int mt = 0; mt < 4; ++mt) {
        const int rowA = wm + mt * 16 + (((lane >> 3) & 1) << 3) + (lane & 7);
        aoff[mt]  = (uint32_t)(rowA * 128);
        amask[mt] = (uint32_t)((rowA & 7) << 4);
    }
    uint32_t boff[2], bmask[2];
    const int bsel = (lane >> 3) & 1;
    #pragma unroll
    for (int p = 0; p < 2; ++p) {
        const int nrow = wn + p * 16 + ((lane >> 4) << 3) + (lane & 7);
        boff[p]  = (uint32_t)(nrow * 128);
        bmask[p] = (uint32_t)((nrow & 7) << 4);
    }

    int hh[4][4][4], md[4][4][4];
    #pragma unroll
    for (int a = 0; a < 4; ++a)
        #pragma unroll
        for (int b = 0; b < 4; ++b)
            #pragma unroll
            for (int c = 0; c < 4; ++c) { hh[a][b][c] = 0; md[a][b][c] = 0; }

    // ---- prologue: fill 3 stages ----
    #pragma unroll
    for (int s = 0; s < 3; ++s) {
        const uint32_t st = sb_addr + s * STAGE_BYTES;
        const int ko = s * BKB;
        #pragma unroll
        for (int i = 0; i < 4; ++i) {
            cp16(st + doff[i],                  pAh + goff[i] + ko);
            cp16(st + TILE_BYTES + doff[i],     pAl + goff[i] + ko);
            cp16(st + 2 * TILE_BYTES + doff[i], pBh + goff[i] + ko);
            cp16(st + 3 * TILE_BYTES + doff[i], pBl + goff[i] + ko);
        }
        cp_commit();
    }

    for (int kt = 0; kt < NKT; ++kt) {
        if (kt < NKT - 2)       cp_wait<2>();
        else if (kt == NKT - 2) cp_wait<1>();
        else                    cp_wait<0>();
        __syncthreads();

        const uint32_t st   = sb_addr + (kt % 3) * STAGE_BYTES;
        const uint32_t stAh = st;
        const uint32_t stAl = st + TILE_BYTES;
        const uint32_t stBh = st + 2 * TILE_BYTES;
        const uint32_t stBl = st + 3 * TILE_BYTES;

        #pragma unroll
        for (int k32 = 0; k32 < 4; ++k32) {
            const uint32_t ka = (uint32_t)((2 * k32 + asel) << 4);
            const uint32_t kb = (uint32_t)((2 * k32 + bsel) << 4);
            uint32_t ah[4][4], al[4][4], bh[2][4], bl[2][4];
            #pragma unroll
            for (int mt = 0; mt < 4; ++mt) {
                ldsm4(ah[mt], stAh + aoff[mt] + (ka ^ amask[mt]));
                ldsm4(al[mt], stAl + aoff[mt] + (ka ^ amask[mt]));
            }
            #pragma unroll
            for (int p = 0; p < 2; ++p) {
                ldsm4(bh[p], stBh + boff[p] + (kb ^ bmask[p]));
                ldsm4(bl[p], stBl + boff[p] + (kb ^ bmask[p]));
            }
            #pragma unroll
            for (int mt = 0; mt < 4; ++mt) {
                #pragma unroll
                for (int nt = 0; nt < 4; ++nt) {
                    const int p = nt >> 1;
                    const int h = (nt & 1) * 2;
                    imma(hh[mt][nt], ah[mt], &bh[p][h]);  // h*h  (weight 2^14)
                    imma(md[mt][nt], ah[mt], &bl[p][h]);  // h*l  (weight 2^7)
                    imma(md[mt][nt], al[mt], &bh[p][h]);  // l*h  (weight 2^7)
                }
            }
        }
        __syncthreads();

        if (kt + 3 < NKT) {
            const int ko = (kt + 3) * BKB;
            #pragma unroll
            for (int i = 0; i < 4; ++i) {
                cp16(st + doff[i],                  pAh + goff[i] + ko);
                cp16(st + TILE_BYTES + doff[i],     pAl + goff[i] + ko);
                cp16(st + 2 * TILE_BYTES + doff[i], pBh + goff[i] + ko);
                cp16(st + 3 * TILE_BYTES + doff[i], pBl + goff[i] + ko);
            }
            cp_commit();
        }
    }

    // ---- epilogue: rescale + bias ----
    #pragma unroll
    for (int mt = 0; mt < 4; ++mt) {
        const int row = m0 + wm + mt * 16 + (lane >> 2);
        const float sa0 = sa[row];
        const float sa8 = sa[row + 8];
        #pragma unroll
        for (int nt = 0; nt < 4; ++nt) {
            const int col = n0 + wn + nt * 8 + (lane & 3) * 2;
            const float2 bb = *(const float2*)&bias[col];
            const float sb0 = sb[col];
            const float sb1 = sb[col + 1];
            float v0 = (float)hh[mt][nt][0] * 16384.0f + (float)md[mt][nt][0] * 128.0f;
            float v1 = (float)hh[mt][nt][1] * 16384.0f + (float)md[mt][nt][1] * 128.0f;
            float v2 = (float)hh[mt][nt][2] * 16384.0f + (float)md[mt][nt][2] * 128.0f;
            float v3 = (float)hh[mt][nt][3] * 16384.0f + (float)md[mt][nt][3] * 128.0f;
            *(float2*)&C[(size_t)row * DFEAT + col] =
                make_float2(sa0 * sb0 * v0 + bb.x, sa0 * sb1 * v1 + bb.y);
            *(float2*)&C[(size_t)(row + 8) * DFEAT + col] =
                make_float2(sa8 * sb0 * v2 + bb.x, sa8 * sb1 * v3 + bb.y);
        }
    }
}

// ---------------- per-token attention (fp32 merged out) ----------------
__global__ __launch_bounds__(256) void attn_kernel(const float* __restrict__ qkv,
                                                   float* __restrict__ merged) {
    __shared__ float qs[64][64];
    __shared__ float kb[64][68];

    const int m = blockIdx.x;
    const int b = m >> 6;
    const int s = m & 63;
    const int tid = threadIdx.x;

    const float* Qp = qkv + (size_t)m * DFEAT;
    const float* Kp = Qp + (size_t)NTOK * DFEAT;
    const float* Vp = Kp + (size_t)NTOK * DFEAT;

    #pragma unroll
    for (int i = 0; i < 4; ++i) {
        const int l = tid + i * 256;
        const int h = l >> 4;
        const int dc = (l & 15) * 4;
        *(float4*)&qs[h][dc] = *(const float4*)(Qp + h * 64 + dc);
        *(float4*)&kb[h][dc] = *(const float4*)(Kp + h * 64 + dc);
    }
    __syncthreads();

    const int ty = tid >> 4;
    const int tx = tid & 15;
    const int i0 = ty * 4;

    float sc[4][4];
    #pragma unroll
    for (int r = 0; r < 4; ++r)
        #pragma unroll
        for (int c = 0; c < 4; ++c) sc[r][c] = 0.0f;

    #pragma unroll
    for (int d4 = 0; d4 < 16; ++d4) {
        float4 qv[4], kv[4];
        #pragma unroll
        for (int r = 0; r < 4; ++r) qv[r] = *(const float4*)&qs[i0 + r][d4 * 4];
        #pragma unroll
        for (int c = 0; c < 4; ++c) kv[c] = *(const float4*)&kb[tx + 16 * c][d4 * 4];
        #pragma unroll
        for (int r = 0; r < 4; ++r)
            #pragma unroll
            for (int c = 0; c < 4; ++c)
                sc[r][c] += qv[r].x * kv[c].x + qv[r].y * kv[c].y +
                            qv[r].z * kv[c].z + qv[r].w * kv[c].w;
    }
    __syncthreads();

    #pragma unroll
    for (int r = 0; r < 4; ++r) {
        #pragma unroll
        for (int c = 0; c < 4; ++c) sc[r][c] *= 0.125f;
        float mx = fmaxf(fmaxf(sc[r][0], sc[r][1]), fmaxf(sc[r][2], sc[r][3]));
        #pragma unroll
        for (int off = 8; off >= 1; off >>= 1)
            mx = fmaxf(mx, __shfl_xor_sync(0xffffffffu, mx, off));
        float sum = 0.0f;
        #pragma unroll
        for (int c = 0; c < 4; ++c) {
            float e = __expf(sc[r][c] - mx);
            sc[r][c] = e;
            sum += e;
        }
        #pragma unroll
        for (int off = 8; off >= 1; off >>= 1)
            sum += __shfl_xor_sync(0xffffffffu, sum, off);
        const float inv = 1.0f / sum;
        #pragma unroll
        for (int c = 0; c < 4; ++c) qs[i0 + r][tx + 16 * c] = sc[r][c] * inv;
    }

    #pragma unroll
    for (int i = 0; i < 4; ++i) {
        const int l = tid + i * 256;
        const int h = l >> 4;
        const int dc = (l & 15) * 4;
        *(float4*)&kb[h][dc] = *(const float4*)(Vp + h * 64 + dc);
    }
    __syncthreads();

    float vv[4][4];
    #pragma unroll
    for (int r = 0; r < 4; ++r)
        #pragma unroll
        for (int c = 0; c < 4; ++c) vv[r][c] = 0.0f;

    #pragma unroll
    for (int k4 = 0; k4 < 16; ++k4) {
        float4 av[4], vb[4];
        #pragma unroll
        for (int r = 0; r < 4; ++r) av[r] = *(const float4*)&qs[i0 + r][k4 * 4];
        #pragma unroll
        for (int c = 0; c < 4; ++c) vb[c] = *(const float4*)&kb[tx + 16 * c][k4 * 4];
        #pragma unroll
        for (int r = 0; r < 4; ++r)
            #pragma unroll
            for (int c = 0; c < 4; ++c)
                vv[r][c] += av[r].x * vb[c].x + av[r].y * vb[c].y +
                            av[r].z * vb[c].z + av[r].w * vb[c].w;
    }

    #pragma unroll
    for (int r = 0; r < 4; ++r)
        #pragma unroll
        for (int c = 0; c < 4; ++c)
            merged[(size_t)(b * 64 + i0 + r) * DFEAT + s * 64 + tx + 16 * c] = vv[r][c];
}

extern "C" void kernel_launch(void* const* d_in, const int* in_sizes, int n_in,
                              void* d_out, int out_size) {
    const float* x  = (const float*)d_in[0];
    const float* Wq = (const float*)d_in[1];
    const float* bq = (const float*)d_in[2];
    const float* Wk = (const float*)d_in[3];
    const float* bk = (const float*)d_in[4];
    const float* Wv = (const float*)d_in[5];
    const float* bv = (const float*)d_in[6];
    const float* Wp = (const float*)d_in[7];
    const float* bp = (const float*)d_in[8];
    float* out = (float*)d_out;

    float *qkv, *merged, *sx, *sw, *sm;
    int8_t *xh, *xl, *wh, *wl, *mh, *ml;
    cudaGetSymbolAddress((void**)&qkv, g_qkv);
    cudaGetSymbolAddress((void**)&merged, g_merged);
    cudaGetSymbolAddress((void**)&xh, g_xh);
    cudaGetSymbolAddress((void**)&xl, g_xl);
    cudaGetSymbolAddress((void**)&wh, g_wh);
    cudaGetSymbolAddress((void**)&wl, g_wl);
    cudaGetSymbolAddress((void**)&mh, g_mh);
    cudaGetSymbolAddress((void**)&ml, g_ml);
    cudaGetSymbolAddress((void**)&sx, g_sx);
    cudaGetSymbolAddress((void**)&sw, g_sw);
    cudaGetSymbolAddress((void**)&sm, g_sm);

    cudaFuncSetAttribute(gemm_imma, cudaFuncAttributeMaxDynamicSharedMemorySize, SMEM_BYTES);

    const size_t MSZ = (size_t)DFEAT * DFEAT;

    // 0) quantize x and weights (per-row 15-bit fixed point)
    quant_rows<<<NTOK, 256>>>(x,  xh, xl, sx);
    quant_rows<<<DFEAT, 256>>>(Wq, wh,          wl,          sw);
    quant_rows<<<DFEAT, 256>>>(Wk, wh + MSZ,    wl + MSZ,    sw + DFEAT);
    quant_rows<<<DFEAT, 256>>>(Wv, wh + 2*MSZ,  wl + 2*MSZ,  sw + 2*DFEAT);
    quant_rows<<<DFEAT, 256>>>(Wp, wh + 3*MSZ,  wl + 3*MSZ,  sw + 3*DFEAT);

    // 1) QKV projections
    GArgs a1;
    a1.Ah = xh; a1.Al = xl; a1.sa = sx;
    a1.Bh[0] = wh;          a1.Bl[0] = wl;          a1.sb[0] = sw;
    a1.Bh[1] = wh + MSZ;    a1.Bl[1] = wl + MSZ;    a1.sb[1] = sw + DFEAT;
    a1.Bh[2] = wh + 2*MSZ;  a1.Bl[2] = wl + 2*MSZ;  a1.sb[2] = sw + 2*DFEAT;
    a1.bias[0] = bq; a1.bias[1] = bk; a1.bias[2] = bv;
    a1.C[0] = qkv;
    a1.C[1] = qkv + (size_t)NTOK * DFEAT;
    a1.C[2] = qkv + 2ull * NTOK * DFEAT;
    gemm_imma<<<dim3(32, 32, 3), 256, SMEM_BYTES>>>(a1);

    // 2) per-token attention -> merged (fp32)
    attn_kernel<<<NTOK, 256>>>(qkv, merged);

    // 2b) quantize merged
    quant_rows<<<NTOK, 256>>>(merged, mh, ml, sm);

    // 3) output projection
    GArgs a2;
    a2.Ah = mh; a2.Al = ml; a2.sa = sm;
    a2.Bh[0] = wh + 3*MSZ; a2.Bl[0] = wl + 3*MSZ; a2.sb[0] = sw + 3*DFEAT;
    a2.Bh[1] = a2.Bh[0];   a2.Bl[1] = a2.Bl[0];   a2.sb[1] = a2.sb[0];
    a2.Bh[2] = a2.Bh[0];   a2.Bl[2] = a2.Bl[0];   a2.sb[2] = a2.sb[0];
    a2.bias[0] = bp; a2.bias[1] = bp; a2.bias[2] = bp;
    a2.C[0] = out; a2.C[1] = out; a2.C[2] = out;
    gemm_imma<<<dim3(32, 32, 1), 256, SMEM_BYTES>>>(a2);
}

// round 6
// speedup vs baseline: 6.6390x; 6.6390x over previous
#include <cuda_runtime.h>
#include <cuda_fp16.h>
#include <stdint.h>

// Problem constants: B=S=H=DH=64, D = H*DH = 4096
static const int DFEAT = 4096;
static const int NTOK  = 4096;

// GEMM tiling: BM=BN=128, BK=64 fp16, 5-stage cp.async pipeline
static const int BK   = 64;
static const int NKT  = DFEAT / BK;              // 64
static const int TILE_BYTES  = 128 * 128;        // 128 rows x 64 fp16 = 16KB
static const int STAGE_BYTES = 2 * TILE_BYTES;   // A, B = 32KB
static const int NSTAGE      = 5;
static const int SMEM_BYTES  = NSTAGE * STAGE_BYTES;  // 160KB

// Scratch (static device arrays; no allocation allowed)
__device__ float  g_qkv[3ull * (size_t)NTOK * DFEAT];
__device__ __half g_xh[(size_t)NTOK * DFEAT];
__device__ __half g_wh[4ull * (size_t)DFEAT * DFEAT];
__device__ __half g_mh[(size_t)NTOK * DFEAT];

struct GArgs {
    const __half* A;
    const __half* B[3];
    const float*  bias[3];
    float*        C[3];
};

// ---------------- helpers ----------------
__device__ __forceinline__ uint32_t smem_u32(const void* p) {
    uint32_t a;
    asm("{ .reg .u64 t; cvta.to.shared.u64 t, %1; cvt.u32.u64 %0, t; }" : "=r"(a) : "l"(p));
    return a;
}
__device__ __forceinline__ void cp16(uint32_t dst, const void* src) {
    asm volatile("cp.async.cg.shared.global [%0], [%1], 16;" :: "r"(dst), "l"(src) : "memory");
}
__device__ __forceinline__ void cp_commit() {
    asm volatile("cp.async.commit_group;" ::: "memory");
}
template <int N>
__device__ __forceinline__ void cp_wait() {
    asm volatile("cp.async.wait_group %0;" :: "n"(N) : "memory");
}
__device__ __forceinline__ void ldsm4(uint32_t* r, uint32_t a) {
    asm volatile("ldmatrix.sync.aligned.m8n8.x4.shared.b16 {%0,%1,%2,%3}, [%4];"
                 : "=r"(r[0]), "=r"(r[1]), "=r"(r[2]), "=r"(r[3]) : "r"(a));
}
__device__ __forceinline__ void mma_f16(float c[4], const uint32_t a[4], const uint32_t b[2]) {
    asm volatile(
        "mma.sync.aligned.m16n8k16.row.col.f32.f16.f16.f32 "
        "{%0,%1,%2,%3}, {%4,%5,%6,%7}, {%8,%9}, {%0,%1,%2,%3};\n"
        : "+f"(c[0]), "+f"(c[1]), "+f"(c[2]), "+f"(c[3])
        : "r"(a[0]), "r"(a[1]), "r"(a[2]), "r"(a[3]), "r"(b[0]), "r"(b[1]));
}

// ---------------- fp32 -> fp16 cast ----------------
__global__ __launch_bounds__(256) void cast_kernel(const float* __restrict__ src,
                                                   __half* __restrict__ dst,
                                                   int n4) {
    const float4* s4 = (const float4*)src;
    uint2* d2 = (uint2*)dst;
    int i = blockIdx.x * blockDim.x + threadIdx.x;
    const int stride = gridDim.x * blockDim.x;
    for (; i < n4; i += stride) {
        float4 v = s4[i];
        __half2 p0 = __floats2half2_rn(v.x, v.y);
        __half2 p1 = __floats2half2_rn(v.z, v.w);
        uint2 o;
        o.x = *(const uint32_t*)&p0;
        o.y = *(const uint32_t*)&p1;
        d2[i] = o;
    }
}

// ---------------- fp16 HMMA GEMM ----------------
// C[m][n] = sum_k A[m][k]*B[n][k] + bias[n]
// 256 threads, warp grid 2(M) x 4(N), warp tile 64x32, BM=BN=128, BK=64.
// 5-stage cp.async pipeline, one __syncthreads per mainloop iteration.
__global__ __launch_bounds__(256, 1) void gemm_hmma(GArgs g) {
    extern __shared__ __align__(1024) char smem[];
    const int z = blockIdx.z;
    const __half* __restrict__ A = g.A;
    const __half* __restrict__ B = g.B[z];
    const float* __restrict__ bias = g.bias[z];
    float* __restrict__ C = g.C[z];

    const int tid  = threadIdx.x;
    const int lane = tid & 31;
    const int wid  = tid >> 5;
    const int wm = (wid & 1) * 64;
    const int wn = (wid >> 1) * 32;
    const int m0 = blockIdx.y * 128;
    const int n0 = blockIdx.x * 128;
    const uint32_t sb = smem_u32(smem);

    // ---- loader mapping: 4 ids per thread, each id = one 16B chunk per tile ----
    uint32_t doff[4];
    int      goff[4];
    #pragma unroll
    for (int i = 0; i < 4; ++i) {
        const int id = tid + i * 256;
        const int r  = id >> 3;      // 0..127
        const int c  = id & 7;       // 16B chunk within 128B row
        doff[i] = (uint32_t)(r * 128 + ((c ^ (r & 7)) << 4));
        goff[i] = r * DFEAT + c * 8; // fp16 element offset
    }
    const __half* pA = A + (size_t)m0 * DFEAT;
    const __half* pB = B + (size_t)n0 * DFEAT;

    // ---- ldmatrix lane mapping ----
    uint32_t aoff[4], amask[4];
    const int asel = lane >> 4;
    #pragma unroll
    for (int mt = 0; mt < 4; ++mt) {
        const int rowA = wm + mt * 16 + (((lane >> 3) & 1) << 3) + (lane & 7);
        aoff[mt]  = (uint32_t)(rowA * 128);
        amask[mt] = (uint32_t)((rowA & 7) << 4);
    }
    uint32_t boff[2], bmask[2];
    const int bsel = (lane >> 3) & 1;
    #pragma unroll
    for (int p = 0; p < 2; ++p) {
        const int nrow = wn + p * 16 + ((lane >> 4) << 3) + (lane & 7);
        boff[p]  = (uint32_t)(nrow * 128);
        bmask[p] = (uint32_t)((nrow & 7) << 4);
    }

    float acc[4][4][4];
    #pragma unroll
    for (int a = 0; a < 4; ++a)
        #pragma unroll
        for (int b = 0; b < 4; ++b)
            #pragma unroll
            for (int c = 0; c < 4; ++c) acc[a][b][c] = 0.0f;

    // ---- prologue: fill 4 of 5 stages ----
    #pragma unroll
    for (int s = 0; s < 4; ++s) {
        const uint32_t st = sb + s * STAGE_BYTES;
        const int ko = s * BK;
        #pragma unroll
        for (int i = 0; i < 4; ++i) {
            cp16(st + doff[i],              pA + goff[i] + ko);
            cp16(st + TILE_BYTES + doff[i], pB + goff[i] + ko);
        }
        cp_commit();
    }

    for (int kt = 0; kt < NKT; ++kt) {
        // ensure stage kt is resident: outstanding-before = min(4, NKT-kt)
        if (kt < NKT - 3)       cp_wait<3>();
        else if (kt == NKT - 3) cp_wait<2>();
        else if (kt == NKT - 2) cp_wait<1>();
        else                    cp_wait<0>();
        __syncthreads();

        // prefetch stage kt+4 into slot (kt+4)%5 (= slot consumed at iter kt-1)
        if (kt + 4 < NKT) {
            const uint32_t stn = sb + ((kt + 4) % NSTAGE) * STAGE_BYTES;
            const int ko = (kt + 4) * BK;
            #pragma unroll
            for (int i = 0; i < 4; ++i) {
                cp16(stn + doff[i],              pA + goff[i] + ko);
                cp16(stn + TILE_BYTES + doff[i], pB + goff[i] + ko);
            }
            cp_commit();
        }

        const uint32_t st  = sb + (kt % NSTAGE) * STAGE_BYTES;
        const uint32_t stA = st;
        const uint32_t stB = st + TILE_BYTES;

        #pragma unroll
        for (int k16 = 0; k16 < 4; ++k16) {
            const uint32_t ka = (uint32_t)((2 * k16 + asel) << 4);
            const uint32_t kb = (uint32_t)((2 * k16 + bsel) << 4);
            uint32_t ah[4][4], bh[2][4];
            #pragma unroll
            for (int mt = 0; mt < 4; ++mt)
                ldsm4(ah[mt], stA + aoff[mt] + (ka ^ amask[mt]));
            #pragma unroll
            for (int p = 0; p < 2; ++p)
                ldsm4(bh[p], stB + boff[p] + (kb ^ bmask[p]));
            #pragma unroll
            for (int mt = 0; mt < 4; ++mt) {
                #pragma unroll
                for (int nt = 0; nt < 4; ++nt) {
                    const int p = nt >> 1;
                    const int h = (nt & 1) * 2;
                    mma_f16(acc[mt][nt], ah[mt], &bh[p][h]);
                }
            }
        }
    }

    // ---- epilogue: bias + fp32 store ----
    #pragma unroll
    for (int mt = 0; mt < 4; ++mt) {
        const int row = m0 + wm + mt * 16 + (lane >> 2);
        #pragma unroll
        for (int nt = 0; nt < 4; ++nt) {
            const int col = n0 + wn + nt * 8 + (lane & 3) * 2;
            const float2 bb = *(const float2*)&bias[col];
            *(float2*)&C[(size_t)row * DFEAT + col] =
                make_float2(acc[mt][nt][0] + bb.x, acc[mt][nt][1] + bb.y);
            *(float2*)&C[(size_t)(row + 8) * DFEAT + col] =
                make_float2(acc[mt][nt][2] + bb.x, acc[mt][nt][3] + bb.y);
        }
    }
}

// ---------------- per-token attention (fp16 merged out) ----------------
__global__ __launch_bounds__(256) void attn_kernel(const float* __restrict__ qkv,
                                                   __half* __restrict__ mh) {
    __shared__ float qs[64][64];
    __shared__ float kb[64][68];

    const int m = blockIdx.x;
    const int b = m >> 6;
    const int s = m & 63;
    const int tid = threadIdx.x;

    const float* Qp = qkv + (size_t)m * DFEAT;
    const float* Kp = Qp + (size_t)NTOK * DFEAT;
    const float* Vp = Kp + (size_t)NTOK * DFEAT;

    #pragma unroll
    for (int i = 0; i < 4; ++i) {
        const int l = tid + i * 256;
        const int h = l >> 4;
        const int dc = (l & 15) * 4;
        *(float4*)&qs[h][dc] = *(const float4*)(Qp + h * 64 + dc);
        *(float4*)&kb[h][dc] = *(const float4*)(Kp + h * 64 + dc);
    }
    __syncthreads();

    const int ty = tid >> 4;
    const int tx = tid & 15;
    const int i0 = ty * 4;

    float sc[4][4];
    #pragma unroll
    for (int r = 0; r < 4; ++r)
        #pragma unroll
        for (int c = 0; c < 4; ++c) sc[r][c] = 0.0f;

    #pragma unroll
    for (int d4 = 0; d4 < 16; ++d4) {
        float4 qv[4], kv[4];
        #pragma unroll
        for (int r = 0; r < 4; ++r) qv[r] = *(const float4*)&qs[i0 + r][d4 * 4];
        #pragma unroll
        for (int c = 0; c < 4; ++c) kv[c] = *(const float4*)&kb[tx + 16 * c][d4 * 4];
        #pragma unroll
        for (int r = 0; r < 4; ++r)
            #pragma unroll
            for (int c = 0; c < 4; ++c)
                sc[r][c] += qv[r].x * kv[c].x + qv[r].y * kv[c].y +
                            qv[r].z * kv[c].z + qv[r].w * kv[c].w;
    }
    __syncthreads();

    #pragma unroll
    for (int r = 0; r < 4; ++r) {
        #pragma unroll
        for (int c = 0; c < 4; ++c) sc[r][c] *= 0.125f;
        float mx = fmaxf(fmaxf(sc[r][0], sc[r][1]), fmaxf(sc[r][2], sc[r][3]));
        #pragma unroll
        for (int off = 8; off >= 1; off >>= 1)
            mx = fmaxf(mx, __shfl_xor_sync(0xffffffffu, mx, off));
        float sum = 0.0f;
        #pragma unroll
        for (int c = 0; c < 4; ++c) {
            float e = __expf(sc[r][c] - mx);
            sc[r][c] = e;
            sum += e;
        }
        #pragma unroll
        for (int off = 8; off >= 1; off >>= 1)
            sum += __shfl_xor_sync(0xffffffffu, sum, off);
        const float inv = 1.0f / sum;
        #pragma unroll
        for (int c = 0; c < 4; ++c) qs[i0 + r][tx + 16 * c] = sc[r][c] * inv;
    }

    #pragma unroll
    for (int i = 0; i < 4; ++i) {
        const int l = tid + i * 256;
        const int h = l >> 4;
        const int dc = (l & 15) * 4;
        *(float4*)&kb[h][dc] = *(const float4*)(Vp + h * 64 + dc);
    }
    __syncthreads();

    float vv[4][4];
    #pragma unroll
    for (int r = 0; r < 4; ++r)
        #pragma unroll
        for (int c = 0; c < 4; ++c) vv[r][c] = 0.0f;

    #pragma unroll
    for (int k4 = 0; k4 < 16; ++k4) {
        float4 av[4], vb[4];
        #pragma unroll
        for (int r = 0; r < 4; ++r) av[r] = *(const float4*)&qs[i0 + r][k4 * 4];
        #pragma unroll
        for (int c = 0; c < 4; ++c) vb[c] = *(const float4*)&kb[tx + 16 * c][k4 * 4];
        #pragma unroll
        for (int r = 0; r < 4; ++r)
            #pragma unroll
            for (int c = 0; c < 4; ++c)
                vv[r][c] += av[r].x * vb[c].x + av[r].y * vb[c].y +
                            av[r].z * vb[c].z + av[r].w * vb[c].w;
    }

    #pragma unroll
    for (int r = 0; r < 4; ++r)
        #pragma unroll
        for (int c = 0; c < 4; ++c)
            mh[(size_t)(b * 64 + i0 + r) * DFEAT + s * 64 + tx + 16 * c] =
                __float2half_rn(vv[r][c]);
}

extern "C" void kernel_launch(void* const* d_in, const int* in_sizes, int n_in,
                              void* d_out, int out_size) {
    const float* x  = (const float*)d_in[0];
    const float* Wq = (const float*)d_in[1];
    const float* bq = (const float*)d_in[2];
    const float* Wk = (const float*)d_in[3];
    const float* bk = (const float*)d_in[4];
    const float* Wv = (const float*)d_in[5];
    const float* bv = (const float*)d_in[6];
    const float* Wp = (const float*)d_in[7];
    const float* bp = (const float*)d_in[8];
    float* out = (float*)d_out;

    float* qkv = nullptr;
    __half *xh, *wh, *mh;
    cudaGetSymbolAddress((void**)&qkv, g_qkv);
    cudaGetSymbolAddress((void**)&xh, g_xh);
    cudaGetSymbolAddress((void**)&wh, g_wh);
    cudaGetSymbolAddress((void**)&mh, g_mh);

    cudaFuncSetAttribute(gemm_hmma, cudaFuncAttributeMaxDynamicSharedMemorySize, SMEM_BYTES);

    const size_t MSZ = (size_t)DFEAT * DFEAT;
    const int n4 = (int)(MSZ / 4);

    // 0) cast x and weights to fp16
    cast_kernel<<<2048, 256>>>(x,  xh,           n4);
    cast_kernel<<<2048, 256>>>(Wq, wh,           n4);
    cast_kernel<<<2048, 256>>>(Wk, wh + MSZ,     n4);
    cast_kernel<<<2048, 256>>>(Wv, wh + 2 * MSZ, n4);
    cast_kernel<<<2048, 256>>>(Wp, wh + 3 * MSZ, n4);

    // 1) QKV projections
    GArgs a1;
    a1.A = xh;
    a1.B[0] = wh;
    a1.B[1] = wh + MSZ;
    a1.B[2] = wh + 2 * MSZ;
    a1.bias[0] = bq; a1.bias[1] = bk; a1.bias[2] = bv;
    a1.C[0] = qkv;
    a1.C[1] = qkv + (size_t)NTOK * DFEAT;
    a1.C[2] = qkv + 2ull * NTOK * DFEAT;
    gemm_hmma<<<dim3(32, 32, 3), 256, SMEM_BYTES>>>(a1);

    // 2) per-token attention -> merged (fp16)
    attn_kernel<<<NTOK, 256>>>(qkv, mh);

    // 3) output projection
    GArgs a2;
    a2.A = mh;
    a2.B[0] = wh + 3 * MSZ;
    a2.B[1] = a2.B[0];
    a2.B[2] = a2.B[0];
    a2.bias[0] = bp; a2.bias[1] = bp; a2.bias[2] = bp;
    a2.C[0] = out; a2.C[1] = out; a2.C[2] = out;
    gemm_hmma<<<dim3(32, 32, 1), 256, SMEM_BYTES>>>(a2);
}

// round 7
// speedup vs baseline: 6.9820x; 1.0517x over previous
#include <cuda_runtime.h>
#include <cuda_fp16.h>
#include <stdint.h>

// Problem constants: B=S=H=DH=64, D = H*DH = 4096
static const int DFEAT = 4096;
static const int NTOK  = 4096;

// GEMM tiling: BM=128, BN=256, BK=64 fp16, 4-stage cp.async pipeline
static const int BK   = 64;
static const int NKT  = DFEAT / BK;               // 64
static const int A_TILE_BYTES = 128 * 128;        // 16KB
static const int B_TILE_BYTES = 256 * 128;        // 32KB
static const int STAGE_BYTES  = A_TILE_BYTES + B_TILE_BYTES;  // 48KB
static const int NSTAGE       = 4;
static const int SMEM_BYTES   = NSTAGE * STAGE_BYTES;         // 192KB

// Scratch (static device arrays; no allocation allowed)
__device__ float  g_qkv[3ull * (size_t)NTOK * DFEAT];
__device__ __half g_xh[(size_t)NTOK * DFEAT];
__device__ __half g_wh[4ull * (size_t)DFEAT * DFEAT];
__device__ __half g_mh[(size_t)NTOK * DFEAT];

struct GArgs {
    const __half* A;
    const __half* B[3];
    const float*  bias[3];
    float*        C[3];
};

// ---------------- helpers ----------------
__device__ __forceinline__ uint32_t smem_u32(const void* p) {
    uint32_t a;
    asm("{ .reg .u64 t; cvta.to.shared.u64 t, %1; cvt.u32.u64 %0, t; }" : "=r"(a) : "l"(p));
    return a;
}
__device__ __forceinline__ void cp16(uint32_t dst, const void* src) {
    asm volatile("cp.async.cg.shared.global [%0], [%1], 16;" :: "r"(dst), "l"(src) : "memory");
}
__device__ __forceinline__ void cp_commit() {
    asm volatile("cp.async.commit_group;" ::: "memory");
}
template <int N>
__device__ __forceinline__ void cp_wait() {
    asm volatile("cp.async.wait_group %0;" :: "n"(N) : "memory");
}
__device__ __forceinline__ void ldsm4(uint32_t* r, uint32_t a) {
    asm volatile("ldmatrix.sync.aligned.m8n8.x4.shared.b16 {%0,%1,%2,%3}, [%4];"
                 : "=r"(r[0]), "=r"(r[1]), "=r"(r[2]), "=r"(r[3]) : "r"(a));
}
__device__ __forceinline__ void mma_f16(float c[4], const uint32_t a[4], const uint32_t b[2]) {
    asm volatile(
        "mma.sync.aligned.m16n8k16.row.col.f32.f16.f16.f32 "
        "{%0,%1,%2,%3}, {%4,%5,%6,%7}, {%8,%9}, {%0,%1,%2,%3};\n"
        : "+f"(c[0]), "+f"(c[1]), "+f"(c[2]), "+f"(c[3])
        : "r"(a[0]), "r"(a[1]), "r"(a[2]), "r"(a[3]), "r"(b[0]), "r"(b[1]));
}

// ---------------- fp32 -> fp16 cast ----------------
__global__ __launch_bounds__(256) void cast_kernel(const float* __restrict__ src,
                                                   __half* __restrict__ dst,
                                                   int n4) {
    const float4* s4 = (const float4*)src;
    uint2* d2 = (uint2*)dst;
    int i = blockIdx.x * blockDim.x + threadIdx.x;
    const int stride = gridDim.x * blockDim.x;
    for (; i < n4; i += stride) {
        float4 v = s4[i];
        __half2 p0 = __floats2half2_rn(v.x, v.y);
        __half2 p1 = __floats2half2_rn(v.z, v.w);
        uint2 o;
        o.x = *(const uint32_t*)&p0;
        o.y = *(const uint32_t*)&p1;
        d2[i] = o;
    }
}

// ---------------- fp16 HMMA GEMM ----------------
// C[m][n] = sum_k A[m][k]*B[n][k] + bias[n]
// 256 threads, warp grid 2(M) x 4(N), warp tile 64x64, BM=128, BN=256, BK=64.
// 4-stage cp.async pipeline, one __syncthreads per mainloop iteration.
__global__ __launch_bounds__(256, 1) void gemm_hmma(GArgs g) {
    extern __shared__ __align__(1024) char smem[];
    const int z = blockIdx.z;
    const __half* __restrict__ A = g.A;
    const __half* __restrict__ B = g.B[z];
    const float* __restrict__ bias = g.bias[z];
    float* __restrict__ C = g.C[z];

    const int tid  = threadIdx.x;
    const int lane = tid & 31;
    const int wid  = tid >> 5;
    const int wm = (wid & 1) * 64;          // 2 warps along M
    const int wn = (wid >> 1) * 64;         // 4 warps along N
    const int m0 = blockIdx.y * 128;
    const int n0 = blockIdx.x * 256;
    const uint32_t sb = smem_u32(smem);

    // ---- loader mapping ----
    // A: 128 rows x 8 chunks = 1024 ids -> 4 per thread
    uint32_t dA[4]; int gA[4];
    #pragma unroll
    for (int i = 0; i < 4; ++i) {
        const int id = tid + i * 256;
        const int r  = id >> 3;
        const int c  = id & 7;
        dA[i] = (uint32_t)(r * 128 + ((c ^ (r & 7)) << 4));
        gA[i] = r * DFEAT + c * 8;
    }
    // B: 256 rows x 8 chunks = 2048 ids -> 8 per thread
    uint32_t dB[8]; int gB[8];
    #pragma unroll
    for (int i = 0; i < 8; ++i) {
        const int id = tid + i * 256;
        const int r  = id >> 3;
        const int c  = id & 7;
        dB[i] = (uint32_t)(r * 128 + ((c ^ (r & 7)) << 4));
        gB[i] = r * DFEAT + c * 8;
    }
    const __half* pA = A + (size_t)m0 * DFEAT;
    const __half* pB = B + (size_t)n0 * DFEAT;

    // ---- ldmatrix lane mapping ----
    uint32_t aoff[4], amask[4];
    const int asel = lane >> 4;
    #pragma unroll
    for (int mt = 0; mt < 4; ++mt) {
        const int rowA = wm + mt * 16 + (((lane >> 3) & 1) << 3) + (lane & 7);
        aoff[mt]  = (uint32_t)(rowA * 128);
        amask[mt] = (uint32_t)((rowA & 7) << 4);
    }
    uint32_t boff[4], bmask[4];
    const int bsel = (lane >> 3) & 1;
    #pragma unroll
    for (int p = 0; p < 4; ++p) {
        const int nrow = wn + p * 16 + ((lane >> 4) << 3) + (lane & 7);
        boff[p]  = (uint32_t)(nrow * 128);
        bmask[p] = (uint32_t)((nrow & 7) << 4);
    }

    float acc[4][8][4];
    #pragma unroll
    for (int a = 0; a < 4; ++a)
        #pragma unroll
        for (int b = 0; b < 8; ++b)
            #pragma unroll
            for (int c = 0; c < 4; ++c) acc[a][b][c] = 0.0f;

    // ---- prologue: fill 3 of 4 stages ----
    #pragma unroll
    for (int s = 0; s < 3; ++s) {
        const uint32_t st = sb + s * STAGE_BYTES;
        const int ko = s * BK;
        #pragma unroll
        for (int i = 0; i < 4; ++i) cp16(st + dA[i], pA + gA[i] + ko);
        #pragma unroll
        for (int i = 0; i < 8; ++i) cp16(st + A_TILE_BYTES + dB[i], pB + gB[i] + ko);
        cp_commit();
    }

    for (int kt = 0; kt < NKT; ++kt) {
        if (kt < NKT - 2)       cp_wait<2>();
        else if (kt == NKT - 2) cp_wait<1>();
        else                    cp_wait<0>();
        __syncthreads();

        // prefetch stage kt+3 into slot (kt+3)%4 (= slot consumed at iter kt-1)
        if (kt + 3 < NKT) {
            const uint32_t stn = sb + ((kt + 3) % NSTAGE) * STAGE_BYTES;
            const int ko = (kt + 3) * BK;
            #pragma unroll
            for (int i = 0; i < 4; ++i) cp16(stn + dA[i], pA + gA[i] + ko);
            #pragma unroll
            for (int i = 0; i < 8; ++i) cp16(stn + A_TILE_BYTES + dB[i], pB + gB[i] + ko);
            cp_commit();
        }

        const uint32_t st  = sb + (kt % NSTAGE) * STAGE_BYTES;
        const uint32_t stA = st;
        const uint32_t stB = st + A_TILE_BYTES;

        #pragma unroll
        for (int k16 = 0; k16 < 4; ++k16) {
            const uint32_t ka = (uint32_t)((2 * k16 + asel) << 4);
            const uint32_t kb = (uint32_t)((2 * k16 + bsel) << 4);
            uint32_t ah[4][4], bh[4][4];
            #pragma unroll
            for (int mt = 0; mt < 4; ++mt)
                ldsm4(ah[mt], stA + aoff[mt] + (ka ^ amask[mt]));
            #pragma unroll
            for (int p = 0; p < 4; ++p)
                ldsm4(bh[p], stB + boff[p] + (kb ^ bmask[p]));
            #pragma unroll
            for (int mt = 0; mt < 4; ++mt) {
                #pragma unroll
                for (int nt = 0; nt < 8; ++nt) {
                    const int p = nt >> 1;
                    const int h = (nt & 1) * 2;
                    mma_f16(acc[mt][nt], ah[mt], &bh[p][h]);
                }
            }
        }
    }

    // ---- epilogue: bias + fp32 store ----
    #pragma unroll
    for (int mt = 0; mt < 4; ++mt) {
        const int row = m0 + wm + mt * 16 + (lane >> 2);
        #pragma unroll
        for (int nt = 0; nt < 8; ++nt) {
            const int col = n0 + wn + nt * 8 + (lane & 3) * 2;
            const float2 bb = *(const float2*)&bias[col];
            *(float2*)&C[(size_t)row * DFEAT + col] =
                make_float2(acc[mt][nt][0] + bb.x, acc[mt][nt][1] + bb.y);
            *(float2*)&C[(size_t)(row + 8) * DFEAT + col] =
                make_float2(acc[mt][nt][2] + bb.x, acc[mt][nt][3] + bb.y);
        }
    }
}

// ---------------- per-token attention (fp16 merged out) ----------------
__global__ __launch_bounds__(256) void attn_kernel(const float* __restrict__ qkv,
                                                   __half* __restrict__ mh) {
    __shared__ float qs[64][64];
    __shared__ float kb[64][68];

    const int m = blockIdx.x;
    const int b = m >> 6;
    const int s = m & 63;
    const int tid = threadIdx.x;

    const float* Qp = qkv + (size_t)m * DFEAT;
    const float* Kp = Qp + (size_t)NTOK * DFEAT;
    const float* Vp = Kp + (size_t)NTOK * DFEAT;

    #pragma unroll
    for (int i = 0; i < 4; ++i) {
        const int l = tid + i * 256;
        const int h = l >> 4;
        const int dc = (l & 15) * 4;
        *(float4*)&qs[h][dc] = *(const float4*)(Qp + h * 64 + dc);
        *(float4*)&kb[h][dc] = *(const float4*)(Kp + h * 64 + dc);
    }
    __syncthreads();

    const int ty = tid >> 4;
    const int tx = tid & 15;
    const int i0 = ty * 4;

    float sc[4][4];
    #pragma unroll
    for (int r = 0; r < 4; ++r)
        #pragma unroll
        for (int c = 0; c < 4; ++c) sc[r][c] = 0.0f;

    #pragma unroll
    for (int d4 = 0; d4 < 16; ++d4) {
        float4 qv[4], kv[4];
        #pragma unroll
        for (int r = 0; r < 4; ++r) qv[r] = *(const float4*)&qs[i0 + r][d4 * 4];
        #pragma unroll
        for (int c = 0; c < 4; ++c) kv[c] = *(const float4*)&kb[tx + 16 * c][d4 * 4];
        #pragma unroll
        for (int r = 0; r < 4; ++r)
            #pragma unroll
            for (int c = 0; c < 4; ++c)
                sc[r][c] += qv[r].x * kv[c].x + qv[r].y * kv[c].y +
                            qv[r].z * kv[c].z + qv[r].w * kv[c].w;
    }
    __syncthreads();

    #pragma unroll
    for (int r = 0; r < 4; ++r) {
        #pragma unroll
        for (int c = 0; c < 4; ++c) sc[r][c] *= 0.125f;
        float mx = fmaxf(fmaxf(sc[r][0], sc[r][1]), fmaxf(sc[r][2], sc[r][3]));
        #pragma unroll
        for (int off = 8; off >= 1; off >>= 1)
            mx = fmaxf(mx, __shfl_xor_sync(0xffffffffu, mx, off));
        float sum = 0.0f;
        #pragma unroll
        for (int c = 0; c < 4; ++c) {
            float e = __expf(sc[r][c] - mx);
            sc[r][c] = e;
            sum += e;
        }
        #pragma unroll
        for (int off = 8; off >= 1; off >>= 1)
            sum += __shfl_xor_sync(0xffffffffu, sum, off);
        const float inv = 1.0f / sum;
        #pragma unroll
        for (int c = 0; c < 4; ++c) qs[i0 + r][tx + 16 * c] = sc[r][c] * inv;
    }

    #pragma unroll
    for (int i = 0; i < 4; ++i) {
        const int l = tid + i * 256;
        const int h = l >> 4;
        const int dc = (l & 15) * 4;
        *(float4*)&kb[h][dc] = *(const float4*)(Vp + h * 64 + dc);
    }
    __syncthreads();

    float vv[4][4];
    #pragma unroll
    for (int r = 0; r < 4; ++r)
        #pragma unroll
        for (int c = 0; c < 4; ++c) vv[r][c] = 0.0f;

    #pragma unroll
    for (int k4 = 0; k4 < 16; ++k4) {
        float4 av[4], vb[4];
        #pragma unroll
        for (int r = 0; r < 4; ++r) av[r] = *(const float4*)&qs[i0 + r][k4 * 4];
        #pragma unroll
        for (int c = 0; c < 4; ++c) vb[c] = *(const float4*)&kb[tx + 16 * c][k4 * 4];
        #pragma unroll
        for (int r = 0; r < 4; ++r)
            #pragma unroll
            for (int c = 0; c < 4; ++c)
                vv[r][c] += av[r].x * vb[c].x + av[r].y * vb[c].y +
                            av[r].z * vb[c].z + av[r].w * vb[c].w;
    }

    #pragma unroll
    for (int r = 0; r < 4; ++r)
        #pragma unroll
        for (int c = 0; c < 4; ++c)
            mh[(size_t)(b * 64 + i0 + r) * DFEAT + s * 64 + tx + 16 * c] =
                __float2half_rn(vv[r][c]);
}

extern "C" void kernel_launch(void* const* d_in, const int* in_sizes, int n_in,
                              void* d_out, int out_size) {
    const float* x  = (const float*)d_in[0];
    const float* Wq = (const float*)d_in[1];
    const float* bq = (const float*)d_in[2];
    const float* Wk = (const float*)d_in[3];
    const float* bk = (const float*)d_in[4];
    const float* Wv = (const float*)d_in[5];
    const float* bv = (const float*)d_in[6];
    const float* Wp = (const float*)d_in[7];
    const float* bp = (const float*)d_in[8];
    float* out = (float*)d_out;

    float* qkv = nullptr;
    __half *xh, *wh, *mh;
    cudaGetSymbolAddress((void**)&qkv, g_qkv);
    cudaGetSymbolAddress((void**)&xh, g_xh);
    cudaGetSymbolAddress((void**)&wh, g_wh);
    cudaGetSymbolAddress((void**)&mh, g_mh);

    cudaFuncSetAttribute(gemm_hmma, cudaFuncAttributeMaxDynamicSharedMemorySize, SMEM_BYTES);

    const size_t MSZ = (size_t)DFEAT * DFEAT;
    const int n4 = (int)(MSZ / 4);

    // 0) cast x and weights to fp16
    cast_kernel<<<2048, 256>>>(x,  xh,           n4);
    cast_kernel<<<2048, 256>>>(Wq, wh,           n4);
    cast_kernel<<<2048, 256>>>(Wk, wh + MSZ,     n4);
    cast_kernel<<<2048, 256>>>(Wv, wh + 2 * MSZ, n4);
    cast_kernel<<<2048, 256>>>(Wp, wh + 3 * MSZ, n4);

    // 1) QKV projections
    GArgs a1;
    a1.A = xh;
    a1.B[0] = wh;
    a1.B[1] = wh + MSZ;
    a1.B[2] = wh + 2 * MSZ;
    a1.bias[0] = bq; a1.bias[1] = bk; a1.bias[2] = bv;
    a1.C[0] = qkv;
    a1.C[1] = qkv + (size_t)NTOK * DFEAT;
    a1.C[2] = qkv + 2ull * NTOK * DFEAT;
    gemm_hmma<<<dim3(16, 32, 3), 256, SMEM_BYTES>>>(a1);

    // 2) per-token attention -> merged (fp16)
    attn_kernel<<<NTOK, 256>>>(qkv, mh);

    // 3) output projection
    GArgs a2;
    a2.A = mh;
    a2.B[0] = wh + 3 * MSZ;
    a2.B[1] = a2.B[0];
    a2.B[2] = a2.B[0];
    a2.bias[0] = bp; a2.bias[1] = bp; a2.bias[2] = bp;
    a2.C[0] = out; a2.C[1] = out; a2.C[2] = out;
    gemm_hmma<<<dim3(16, 32, 1), 256, SMEM_BYTES>>>(a2);
}

// round 8
// speedup vs baseline: 7.9182x; 1.1341x over previous
#include <cuda_runtime.h>
#include <cuda_fp16.h>
#include <stdint.h>

// Problem constants: B=S=H=DH=64, D = H*DH = 4096
static const int DFEAT = 4096;
static const int NTOK  = 4096;

// GEMM tiling: BM=BN=128, BK=64 fp16, 3-stage cp.async pipeline, 2 CTAs/SM
static const int BK   = 64;
static const int NKT  = DFEAT / BK;              // 64
static const int TILE_BYTES  = 128 * 128;        // 16KB
static const int STAGE_BYTES = 2 * TILE_BYTES;   // A, B = 32KB
static const int NSTAGE      = 3;
static const int SMEM_BYTES  = NSTAGE * STAGE_BYTES;  // 96KB

// Scratch (static device arrays; no allocation allowed)
__device__ float  g_qkv[3ull * (size_t)NTOK * DFEAT];
__device__ __half g_xh[(size_t)NTOK * DFEAT];
__device__ __half g_wh[4ull * (size_t)DFEAT * DFEAT];
__device__ __half g_mh[(size_t)NTOK * DFEAT];

struct GArgs {
    const __half* A;
    const __half* B[3];
    const float*  bias[3];
    float*        C[3];
};

// ---------------- helpers ----------------
__device__ __forceinline__ uint32_t smem_u32(const void* p) {
    uint32_t a;
    asm("{ .reg .u64 t; cvta.to.shared.u64 t, %1; cvt.u32.u64 %0, t; }" : "=r"(a) : "l"(p));
    return a;
}
__device__ __forceinline__ void cp16(uint32_t dst, const void* src) {
    asm volatile("cp.async.cg.shared.global [%0], [%1], 16;" :: "r"(dst), "l"(src) : "memory");
}
__device__ __forceinline__ void cp_commit() {
    asm volatile("cp.async.commit_group;" ::: "memory");
}
template <int N>
__device__ __forceinline__ void cp_wait() {
    asm volatile("cp.async.wait_group %0;" :: "n"(N) : "memory");
}
__device__ __forceinline__ void ldsm4(uint32_t* r, uint32_t a) {
    asm volatile("ldmatrix.sync.aligned.m8n8.x4.shared.b16 {%0,%1,%2,%3}, [%4];"
                 : "=r"(r[0]), "=r"(r[1]), "=r"(r[2]), "=r"(r[3]) : "r"(a));
}
__device__ __forceinline__ void mma_f16(float c[4], const uint32_t a[4], const uint32_t b[2]) {
    asm volatile(
        "mma.sync.aligned.m16n8k16.row.col.f32.f16.f16.f32 "
        "{%0,%1,%2,%3}, {%4,%5,%6,%7}, {%8,%9}, {%0,%1,%2,%3};\n"
        : "+f"(c[0]), "+f"(c[1]), "+f"(c[2]), "+f"(c[3])
        : "r"(a[0]), "r"(a[1]), "r"(a[2]), "r"(a[3]), "r"(b[0]), "r"(b[1]));
}

// ---------------- fp32 -> fp16 cast ----------------
__global__ __launch_bounds__(256) void cast_kernel(const float* __restrict__ src,
                                                   __half* __restrict__ dst,
                                                   int n4) {
    const float4* s4 = (const float4*)src;
    uint2* d2 = (uint2*)dst;
    int i = blockIdx.x * blockDim.x + threadIdx.x;
    const int stride = gridDim.x * blockDim.x;
    for (; i < n4; i += stride) {
        float4 v = s4[i];
        __half2 p0 = __floats2half2_rn(v.x, v.y);
        __half2 p1 = __floats2half2_rn(v.z, v.w);
        uint2 o;
        o.x = *(const uint32_t*)&p0;
        o.y = *(const uint32_t*)&p1;
        d2[i] = o;
    }
}

// ---------------- fp16 HMMA GEMM ----------------
// C[m][n] = sum_k A[m][k]*B[n][k] + bias[n]
// 256 threads, warp grid 2(M) x 4(N), warp tile 64x32, BM=BN=128, BK=64.
// 3-stage cp.async pipeline, 2 CTAs/SM for barrier-bubble overlap.
__global__ __launch_bounds__(256, 2) void gemm_hmma(GArgs g) {
    extern __shared__ __align__(1024) char smem[];
    const int z = blockIdx.z;
    const __half* __restrict__ A = g.A;
    const __half* __restrict__ B = g.B[z];
    const float* __restrict__ bias = g.bias[z];
    float* __restrict__ C = g.C[z];

    const int tid  = threadIdx.x;
    const int lane = tid & 31;
    const int wid  = tid >> 5;
    const int wm = (wid & 1) * 64;
    const int wn = (wid >> 1) * 32;
    const int m0 = blockIdx.y * 128;
    const int n0 = blockIdx.x * 128;
    const uint32_t sb = smem_u32(smem);

    // ---- loader mapping: 4 ids per thread, each id = one 16B chunk per tile ----
    uint32_t doff[4];
    int      goff[4];
    #pragma unroll
    for (int i = 0; i < 4; ++i) {
        const int id = tid + i * 256;
        const int r  = id >> 3;      // 0..127
        const int c  = id & 7;       // 16B chunk within 128B row
        doff[i] = (uint32_t)(r * 128 + ((c ^ (r & 7)) << 4));
        goff[i] = r * DFEAT + c * 8; // fp16 element offset
    }
    const __half* pA = A + (size_t)m0 * DFEAT;
    const __half* pB = B + (size_t)n0 * DFEAT;

    // ---- ldmatrix lane mapping ----
    uint32_t aoff[4], amask[4];
    const int asel = lane >> 4;
    #pragma unroll
    for (int mt = 0; mt < 4; ++mt) {
        const int rowA = wm + mt * 16 + (((lane >> 3) & 1) << 3) + (lane & 7);
        aoff[mt]  = (uint32_t)(rowA * 128);
        amask[mt] = (uint32_t)((rowA & 7) << 4);
    }
    uint32_t boff[2], bmask[2];
    const int bsel = (lane >> 3) & 1;
    #pragma unroll
    for (int p = 0; p < 2; ++p) {
        const int nrow = wn + p * 16 + ((lane >> 4) << 3) + (lane & 7);
        boff[p]  = (uint32_t)(nrow * 128);
        bmask[p] = (uint32_t)((nrow & 7) << 4);
    }

    float acc[4][4][4];
    #pragma unroll
    for (int a = 0; a < 4; ++a)
        #pragma unroll
        for (int b = 0; b < 4; ++b)
            #pragma unroll
            for (int c = 0; c < 4; ++c) acc[a][b][c] = 0.0f;

    // ---- prologue: fill 2 of 3 stages ----
    #pragma unroll
    for (int s = 0; s < 2; ++s) {
        const uint32_t st = sb + s * STAGE_BYTES;
        const int ko = s * BK;
        #pragma unroll
        for (int i = 0; i < 4; ++i) {
            cp16(st + doff[i],              pA + goff[i] + ko);
            cp16(st + TILE_BYTES + doff[i], pB + goff[i] + ko);
        }
        cp_commit();
    }

    for (int kt = 0; kt < NKT; ++kt) {
        if (kt < NKT - 1) cp_wait<1>();
        else              cp_wait<0>();
        __syncthreads();

        // prefetch stage kt+2 into slot (kt+2)%3 (= slot consumed at iter kt-1)
        if (kt + 2 < NKT) {
            const uint32_t stn = sb + ((kt + 2) % NSTAGE) * STAGE_BYTES;
            const int ko = (kt + 2) * BK;
            #pragma unroll
            for (int i = 0; i < 4; ++i) {
                cp16(stn + doff[i],              pA + goff[i] + ko);
                cp16(stn + TILE_BYTES + doff[i], pB + goff[i] + ko);
            }
            cp_commit();
        }

        const uint32_t st  = sb + (kt % NSTAGE) * STAGE_BYTES;
        const uint32_t stA = st;
        const uint32_t stB = st + TILE_BYTES;

        #pragma unroll
        for (int k16 = 0; k16 < 4; ++k16) {
            const uint32_t ka = (uint32_t)((2 * k16 + asel) << 4);
            const uint32_t kb = (uint32_t)((2 * k16 + bsel) << 4);
            uint32_t ah[4][4], bh[2][4];
            #pragma unroll
            for (int mt = 0; mt < 4; ++mt)
                ldsm4(ah[mt], stA + aoff[mt] + (ka ^ amask[mt]));
            #pragma unroll
            for (int p = 0; p < 2; ++p)
                ldsm4(bh[p], stB + boff[p] + (kb ^ bmask[p]));
            #pragma unroll
            for (int mt = 0; mt < 4; ++mt) {
                #pragma unroll
                for (int nt = 0; nt < 4; ++nt) {
                    const int p = nt >> 1;
                    const int h = (nt & 1) * 2;
                    mma_f16(acc[mt][nt], ah[mt], &bh[p][h]);
                }
            }
        }
    }

    // ---- epilogue: bias + fp32 store ----
    #pragma unroll
    for (int mt = 0; mt < 4; ++mt) {
        const int row = m0 + wm + mt * 16 + (lane >> 2);
        #pragma unroll
        for (int nt = 0; nt < 4; ++nt) {
            const int col = n0 + wn + nt * 8 + (lane & 3) * 2;
            const float2 bb = *(const float2*)&bias[col];
            *(float2*)&C[(size_t)row * DFEAT + col] =
                make_float2(acc[mt][nt][0] + bb.x, acc[mt][nt][1] + bb.y);
            *(float2*)&C[(size_t)(row + 8) * DFEAT + col] =
                make_float2(acc[mt][nt][2] + bb.x, acc[mt][nt][3] + bb.y);
        }
    }
}

// ---------------- per-token attention (fp16 merged out) ----------------
__global__ __launch_bounds__(256) void attn_kernel(const float* __restrict__ qkv,
                                                   __half* __restrict__ mh) {
    __shared__ float qs[64][64];
    __shared__ float kb[64][68];

    const int m = blockIdx.x;
    const int b = m >> 6;
    const int s = m & 63;
    const int tid = threadIdx.x;

    const float* Qp = qkv + (size_t)m * DFEAT;
    const float* Kp = Qp + (size_t)NTOK * DFEAT;
    const float* Vp = Kp + (size_t)NTOK * DFEAT;

    #pragma unroll
    for (int i = 0; i < 4; ++i) {
        const int l = tid + i * 256;
        const int h = l >> 4;
        const int dc = (l & 15) * 4;
        *(float4*)&qs[h][dc] = *(const float4*)(Qp + h * 64 + dc);
        *(float4*)&kb[h][dc] = *(const float4*)(Kp + h * 64 + dc);
    }
    __syncthreads();

    const int ty = tid >> 4;
    const int tx = tid & 15;
    const int i0 = ty * 4;

    float sc[4][4];
    #pragma unroll
    for (int r = 0; r < 4; ++r)
        #pragma unroll
        for (int c = 0; c < 4; ++c) sc[r][c] = 0.0f;

    #pragma unroll
    for (int d4 = 0; d4 < 16; ++d4) {
        float4 qv[4], kv[4];
        #pragma unroll
        for (int r = 0; r < 4; ++r) qv[r] = *(const float4*)&qs[i0 + r][d4 * 4];
        #pragma unroll
        for (int c = 0; c < 4; ++c) kv[c] = *(const float4*)&kb[tx + 16 * c][d4 * 4];
        #pragma unroll
        for (int r = 0; r < 4; ++r)
            #pragma unroll
            for (int c = 0; c < 4; ++c)
                sc[r][c] += qv[r].x * kv[c].x + qv[r].y * kv[c].y +
                            qv[r].z * kv[c].z + qv[r].w * kv[c].w;
    }
    __syncthreads();

    #pragma unroll
    for (int r = 0; r < 4; ++r) {
        #pragma unroll
        for (int c = 0; c < 4; ++c) sc[r][c] *= 0.125f;
        float mx = fmaxf(fmaxf(sc[r][0], sc[r][1]), fmaxf(sc[r][2], sc[r][3]));
        #pragma unroll
        for (int off = 8; off >= 1; off >>= 1)
            mx = fmaxf(mx, __shfl_xor_sync(0xffffffffu, mx, off));
        float sum = 0.0f;
        #pragma unroll
        for (int c = 0; c < 4; ++c) {
            float e = __expf(sc[r][c] - mx);
            sc[r][c] = e;
            sum += e;
        }
        #pragma unroll
        for (int off = 8; off >= 1; off >>= 1)
            sum += __shfl_xor_sync(0xffffffffu, sum, off);
        const float inv = 1.0f / sum;
        #pragma unroll
        for (int c = 0; c < 4; ++c) qs[i0 + r][tx + 16 * c] = sc[r][c] * inv;
    }

    #pragma unroll
    for (int i = 0; i < 4; ++i) {
        const int l = tid + i * 256;
        const int h = l >> 4;
        const int dc = (l & 15) * 4;
        *(float4*)&kb[h][dc] = *(const float4*)(Vp + h * 64 + dc);
    }
    __syncthreads();

    float vv[4][4];
    #pragma unroll
    for (int r = 0; r < 4; ++r)
        #pragma unroll
        for (int c = 0; c < 4; ++c) vv[r][c] = 0.0f;

    #pragma unroll
    for (int k4 = 0; k4 < 16; ++k4) {
        float4 av[4], vb[4];
        #pragma unroll
        for (int r = 0; r < 4; ++r) av[r] = *(const float4*)&qs[i0 + r][k4 * 4];
        #pragma unroll
        for (int c = 0; c < 4; ++c) vb[c] = *(const float4*)&kb[tx + 16 * c][k4 * 4];
        #pragma unroll
        for (int r = 0; r < 4; ++r)
            #pragma unroll
            for (int c = 0; c < 4; ++c)
                vv[r][c] += av[r].x * vb[c].x + av[r].y * vb[c].y +
                            av[r].z * vb[c].z + av[r].w * vb[c].w;
    }

    #pragma unroll
    for (int r = 0; r < 4; ++r)
        #pragma unroll
        for (int c = 0; c < 4; ++c)
            mh[(size_t)(b * 64 + i0 + r) * DFEAT + s * 64 + tx + 16 * c] =
                __float2half_rn(vv[r][c]);
}

extern "C" void kernel_launch(void* const* d_in, const int* in_sizes, int n_in,
                              void* d_out, int out_size) {
    const float* x  = (const float*)d_in[0];
    const float* Wq = (const float*)d_in[1];
    const float* bq = (const float*)d_in[2];
    const float* Wk = (const float*)d_in[3];
    const float* bk = (const float*)d_in[4];
    const float* Wv = (const float*)d_in[5];
    const float* bv = (const float*)d_in[6];
    const float* Wp = (const float*)d_in[7];
    const float* bp = (const float*)d_in[8];
    float* out = (float*)d_out;

    float* qkv = nullptr;
    __half *xh, *wh, *mh;
    cudaGetSymbolAddress((void**)&qkv, g_qkv);
    cudaGetSymbolAddress((void**)&xh, g_xh);
    cudaGetSymbolAddress((void**)&wh, g_wh);
    cudaGetSymbolAddress((void**)&mh, g_mh);

    cudaFuncSetAttribute(gemm_hmma, cudaFuncAttributeMaxDynamicSharedMemorySize, SMEM_BYTES);

    const size_t MSZ = (size_t)DFEAT * DFEAT;
    const int n4 = (int)(MSZ / 4);

    // 0) cast x and weights to fp16
    cast_kernel<<<2048, 256>>>(x,  xh,           n4);
    cast_kernel<<<2048, 256>>>(Wq, wh,           n4);
    cast_kernel<<<2048, 256>>>(Wk, wh + MSZ,     n4);
    cast_kernel<<<2048, 256>>>(Wv, wh + 2 * MSZ, n4);
    cast_kernel<<<2048, 256>>>(Wp, wh + 3 * MSZ, n4);

    // 1) QKV projections
    GArgs a1;
    a1.A = xh;
    a1.B[0] = wh;
    a1.B[1] = wh + MSZ;
    a1.B[2] = wh + 2 * MSZ;
    a1.bias[0] = bq; a1.bias[1] = bk; a1.bias[2] = bv;
    a1.C[0] = qkv;
    a1.C[1] = qkv + (size_t)NTOK * DFEAT;
    a1.C[2] = qkv + 2ull * NTOK * DFEAT;
    gemm_hmma<<<dim3(32, 32, 3), 256, SMEM_BYTES>>>(a1);

    // 2) per-token attention -> merged (fp16)
    attn_kernel<<<NTOK, 256>>>(qkv, mh);

    // 3) output projection
    GArgs a2;
    a2.A = mh;
    a2.B[0] = wh + 3 * MSZ;
    a2.B[1] = a2.B[0];
    a2.B[2] = a2.B[0];
    a2.bias[0] = bp; a2.bias[1] = bp; a2.bias[2] = bp;
    a2.C[0] = out; a2.C[1] = out; a2.C[2] = out;
    gemm_hmma<<<dim3(32, 32, 1), 256, SMEM_BYTES>>>(a2);
}